// round 6
// baseline (speedup 1.0000x reference)
#include <cuda_runtime.h>
#include <cstdint>

// ---------------------------------------------------------------------------
// Problem: onsets (B=64, T=8192, N=16, C=2) fp32.
//   onset[b,t] = any(onsets[b,t,n,0] > 0 over n)
//   out[b,t]   = t - (index of most recent onset <= t, else -1)   (fp32)
// ---------------------------------------------------------------------------

static constexpr int B = 64;
static constexpr int T = 8192;
static constexpr int WORDS_PER_B = T / 32;          // 256
static constexpr int TOTAL_WORDS = B * WORDS_PER_B; // 16384

// Scratch bitmask: bit (t%32) of word (b*256 + t/32) = onset flag at (b,t).
__device__ uint32_t g_onset_mask[TOTAL_WORDS];

// ---------------------------------------------------------------------------
// Pass 1: stream 64 MiB, emit the onset bitmask (full-chip, DRAM-bound).
// One thread per frame t_global in [0, B*T). Each (b,t) row is 32 contiguous
// floats = 128 B = 8 float4. Channel 0 lives at even float positions, i.e.
// .x and .z of every float4.
// ---------------------------------------------------------------------------
__global__ void __launch_bounds__(256)
onset_flags_kernel(const float4* __restrict__ in)
{
    const int tg = blockIdx.x * 256 + threadIdx.x;   // global frame id
    const float4* p = in + (size_t)tg * 8;

    float m = 0.0f;
    #pragma unroll
    for (int i = 0; i < 8; i++) {
        float4 v = __ldcs(p + i);                    // streaming: no L2 reuse
        m = fmaxf(m, fmaxf(v.x, v.z));
    }

    unsigned bal = __ballot_sync(0xFFFFFFFFu, m > 0.0f);
    if ((threadIdx.x & 31) == 0)
        g_onset_mask[tg >> 5] = bal;
}

// ---------------------------------------------------------------------------
// Pass 2: per-batch scan over 8192 frames. One CTA per b, 256 threads, each
// thread owns one 32-bit word (32 frames).
//   local  = highest set bit index in my word (global frame id), else -1
//   excl   = max of local over all earlier words in this batch (exclusive),
//            seeded with -1 (the virtual onset at index -1)
//   per bit j: last = (bits <= j set in word) ? highest such bit : excl
//              out  = float(t - last)
// ---------------------------------------------------------------------------
__global__ void __launch_bounds__(256)
onset_scan_kernel(float* __restrict__ out)
{
    const int b   = blockIdx.x;
    const int tid = threadIdx.x;            // 0..255
    const int lane = tid & 31;
    const int wid  = tid >> 5;              // 0..7

    const uint32_t word = g_onset_mask[b * WORDS_PER_B + tid];
    const int tb = tid * 32;                // first frame of this word (within b)

    // last onset index inside this word (or -1)
    int v = word ? (tb + 31 - __clz(word)) : -1;

    // warp-inclusive max scan
    #pragma unroll
    for (int off = 1; off < 32; off <<= 1) {
        int u = __shfl_up_sync(0xFFFFFFFFu, v, off);
        if (lane >= off) v = max(v, u);
    }

    __shared__ int warp_max[8];
    if (lane == 31) warp_max[wid] = v;
    __syncthreads();

    // exclusive prefix across warps (8 warps -> tiny serial max)
    int wpre = -1;
    #pragma unroll
    for (int i = 0; i < 8; i++)
        if (i < wid) wpre = max(wpre, warp_max[i]);

    // exclusive within warp: inclusive value of lane-1
    int up = __shfl_up_sync(0xFFFFFFFFu, v, 1);
    int excl = (lane == 0) ? wpre : max(wpre, up);

    // emit 32 frames as 8 float4 stores
    float4* dst = reinterpret_cast<float4*>(out + (size_t)b * T + tb);
    #pragma unroll
    for (int q = 0; q < 8; q++) {
        float o[4];
        #pragma unroll
        for (int k = 0; k < 4; k++) {
            int j = q * 4 + k;                              // bit within word
            uint32_t msk = word & (0xFFFFFFFFu >> (31 - j)); // bits <= j
            int last = msk ? (tb + 31 - __clz(msk)) : excl;
            o[k] = (float)(tb + j - last);
        }
        dst[q] = make_float4(o[0], o[1], o[2], o[3]);
    }
}

// ---------------------------------------------------------------------------
extern "C" void kernel_launch(void* const* d_in, const int* in_sizes, int n_in,
                              void* d_out, int out_size)
{
    const float4* in = (const float4*)d_in[0];
    float* out = (float*)d_out;

    onset_flags_kernel<<<(B * T) / 256, 256>>>(in);
    onset_scan_kernel<<<B, 256>>>(out);
}

// round 7
// speedup vs baseline: 3.1078x; 3.1078x over previous
#include <cuda_runtime.h>
#include <cstdint>

// ---------------------------------------------------------------------------
// onsets (B=64, T=8192, N=16, C=2) fp32.
//   onset[b,t] = any(onsets[b,t,n,0] > 0 over n)
//   out[b,t]   = t - (index of most recent onset <= t, else -1)   (fp32)
// ---------------------------------------------------------------------------

static constexpr int B = 64;
static constexpr int T = 8192;
static constexpr int WORDS_PER_B = T / 32;          // 256
static constexpr int TOTAL_WORDS = B * WORDS_PER_B; // 16384
static constexpr int CHUNKS = 8;                    // chunks per batch (pass 2)
static constexpr int WORDS_PER_CHUNK = WORDS_PER_B / CHUNKS; // 32

// Scratch bitmask: bit (t%32) of word (b*256 + t/32) = onset flag at (b,t).
__device__ uint32_t g_onset_mask[TOTAL_WORDS];

// ---------------------------------------------------------------------------
// Pass 1: stream 64 MiB -> 64 KiB bitmask. One warp per 32 frames.
// Iteration i: warp loads 512 B contiguous (32 lanes x float4); frame f's
// channel-0 maxes live in .x/.z of 8 adjacent lanes. Loads are batched into
// registers first (MLP=8), then 8 ballots assemble the 32-bit mask word.
// ---------------------------------------------------------------------------
__global__ void __launch_bounds__(256)
onset_flags_kernel(const float4* __restrict__ in)
{
    const int warp = (blockIdx.x * 256 + threadIdx.x) >> 5; // global warp id
    const int lane = threadIdx.x & 31;

    // warp covers frames [warp*32, warp*32+32) = float4 [warp*256, warp*256+256)
    const float4* p = in + (size_t)warp * 256 + lane;

    float m[8];
    #pragma unroll
    for (int i = 0; i < 8; i++) {
        float4 v = __ldcs(p + i * 32);          // streaming, 512B/warp/iter
        m[i] = fmaxf(v.x, v.z);                 // channel 0 at even floats
    }

    uint32_t bits = 0;
    #pragma unroll
    for (int i = 0; i < 8; i++) {
        unsigned bal = __ballot_sync(0xFFFFFFFFu, m[i] > 0.0f);
        #pragma unroll
        for (int j = 0; j < 4; j++)             // 4 frames per iteration
            bits |= (((bal >> (8 * j)) & 0xFFu) ? 1u : 0u) << (i * 4 + j);
    }

    if (lane == 0)
        g_onset_mask[warp] = bits;
}

// ---------------------------------------------------------------------------
// Pass 2: grid = B*CHUNKS CTAs, 256 threads. CTA (b, chunk) handles 1024
// frames. It (a) reduces the <=224 earlier mask words of batch b to get the
// exclusive "last onset" prefix (redundant across chunks but L2-hot and
// tiny), (b) warp-scans the 32 words of its chunk, (c) each thread emits 4
// frames as one float4 (fully coalesced 4 KiB per CTA).
// ---------------------------------------------------------------------------
__global__ void __launch_bounds__(256)
onset_scan_kernel(float* __restrict__ out)
{
    const int b     = blockIdx.x >> 3;
    const int chunk = blockIdx.x & 7;
    const int tid   = threadIdx.x;
    const int lane  = tid & 31;
    const int wid   = tid >> 5;

    const uint32_t* __restrict__ mask = g_onset_mask + b * WORDS_PER_B;
    const int w0 = chunk * WORDS_PER_CHUNK;     // first word of this chunk

    __shared__ int s_warpmax[8];
    __shared__ int s_pre;                        // exclusive prefix at w0
    __shared__ int s_wpre[WORDS_PER_CHUNK];      // per-word exclusive prefix

    // (a) max last-onset index over words [0, w0)   (w0 <= 224 < 256)
    int pre = -1;
    if (tid < w0) {
        uint32_t w = mask[tid];
        if (w) pre = tid * 32 + 31 - __clz(w);
    }
    #pragma unroll
    for (int off = 16; off; off >>= 1)
        pre = max(pre, __shfl_xor_sync(0xFFFFFFFFu, pre, off));
    if (lane == 0) s_warpmax[wid] = pre;
    __syncthreads();
    if (tid == 0) {
        int mx = -1;
        #pragma unroll
        for (int i = 0; i < 8; i++) mx = max(mx, s_warpmax[i]);
        s_pre = mx;                              // -1 = virtual onset at t=-1
    }
    __syncthreads();

    // (b) exclusive max-scan over the chunk's 32 words (warp 0)
    if (tid < 32) {
        uint32_t w = mask[w0 + tid];
        int v = w ? ((w0 + tid) * 32 + 31 - __clz(w)) : -1;
        #pragma unroll
        for (int off = 1; off < 32; off <<= 1) {
            int u = __shfl_up_sync(0xFFFFFFFFu, v, off);
            if (lane >= off) v = max(v, u);
        }
        int up = __shfl_up_sync(0xFFFFFFFFu, v, 1);
        int sp = s_pre;
        s_wpre[tid] = (tid == 0) ? sp : max(sp, up);
    }
    __syncthreads();

    // (c) thread tid -> word tid/8, nibble tid%8 -> frames [4*tid, 4*tid+4)
    const int wloc = tid >> 3;
    const int nib  = tid & 7;
    const uint32_t word = mask[w0 + wloc];       // 8-way broadcast, L1-hot
    const int tbase = (w0 + wloc) * 32;          // frame base of this word
    const int excl  = s_wpre[wloc];

    float o[4];
    #pragma unroll
    for (int k = 0; k < 4; k++) {
        int j = nib * 4 + k;                               // bit within word
        uint32_t mk = word & (0xFFFFFFFFu >> (31 - j));    // bits <= j
        int last = mk ? (tbase + 31 - __clz(mk)) : excl;
        o[k] = (float)(tbase + j - last);
    }
    reinterpret_cast<float4*>(out + (size_t)b * T + w0 * 32)[tid] =
        make_float4(o[0], o[1], o[2], o[3]);
}

// ---------------------------------------------------------------------------
extern "C" void kernel_launch(void* const* d_in, const int* in_sizes, int n_in,
                              void* d_out, int out_size)
{
    const float4* in = (const float4*)d_in[0];
    float* out = (float*)d_out;

    onset_flags_kernel<<<(B * T / 32) / 8, 256>>>(in);   // 2048 CTAs
    onset_scan_kernel<<<B * CHUNKS, 256>>>(out);         // 512 CTAs
}